// round 13
// baseline (speedup 1.0000x reference)
#include <cuda_runtime.h>
#include <cuda_fp16.h>
#include <math.h>
#include <float.h>
#include <stdint.h>

#define BHN  32
#define LSEQ 2048
#define DIM  128
#define BLK  64
#define NB   32
#define TOP  4
#define NCH  8
#define CHL  (LSEQ/NCH)   // 256 (2 sub-chunks of 128)

// ---- scratch ----
__device__ __half g_qh[(size_t)BHN*LSEQ*DIM];    // fp16 q [bh][l][d]
__device__ __half g_kh[(size_t)BHN*LSEQ*DIM];    // fp16 k [bh][l][d]
__device__ __half g_vth[(size_t)BHN*DIM*LSEQ];   // fp16 v^T [bh][d][l]
__device__ __half g_phiqh[(size_t)BHN*LSEQ*DIM]; // fp16 phi_q [bh][l][d]
__device__ __half g_phikt[(size_t)BHN*DIM*LSEQ]; // fp16 phi_k^T [bh][d][l]
__device__ float  g_qb[BHN*NB*DIM];
__device__ float  g_kb[BHN*NB*DIM];
__device__ int    g_lut[BHN*NB*TOP];
__device__ float  g_ksum[BHN*DIM];
__device__ float  g_kv_part[(size_t)NCH*BHN*DIM*DIM];
__device__ float  g_ksum_part[NCH*BHN*DIM];
__device__ __half g_mt[BHN*DIM*DIM];             // (kv@W^T)^T : [bh][e2][d]

// ---- helpers ----
__device__ __forceinline__ uint32_t h2(float a, float b) {
    __half2 h = __floats2half2_rn(a, b);
    return *(uint32_t*)&h;
}
__device__ __forceinline__ void mma16(float* c,
        uint32_t a0, uint32_t a1, uint32_t a2, uint32_t a3,
        uint32_t b0, uint32_t b1) {
    asm volatile(
        "mma.sync.aligned.m16n8k16.row.col.f32.f16.f16.f32 "
        "{%0,%1,%2,%3},{%4,%5,%6,%7},{%8,%9},{%0,%1,%2,%3};\n"
        : "+f"(c[0]), "+f"(c[1]), "+f"(c[2]), "+f"(c[3])
        : "r"(a0), "r"(a1), "r"(a2), "r"(a3), "r"(b0), "r"(b1));
}
__device__ __forceinline__ uint32_t s2u(const void* p) {
    uint32_t a;
    asm("{ .reg .u64 t; cvta.to.shared.u64 t, %1; cvt.u32.u64 %0, t; }" : "=r"(a) : "l"(p));
    return a;
}
__device__ __forceinline__ void cpa16(uint32_t s, const void* g) {
    asm volatile("cp.async.cg.shared.global [%0],[%1],16;\n" :: "r"(s), "l"(g));
}
#define CP_COMMIT() asm volatile("cp.async.commit_group;\n")
#define CP_WAIT(n)  asm volatile("cp.async.wait_group " #n ";\n")

__device__ __forceinline__ void ldsm4(uint32_t& r0, uint32_t& r1,
                                      uint32_t& r2, uint32_t& r3, uint32_t sa) {
    asm volatile("ldmatrix.sync.aligned.m8n8.x4.shared.b16 {%0,%1,%2,%3}, [%4];"
        : "=r"(r0), "=r"(r1), "=r"(r2), "=r"(r3) : "r"(sa));
}
#define A_ADDR(PTR, M0, STR) \
    (s2u(PTR) + (((M0) + (lane&7) + ((lane>>3)&1)*8)*(STR) + (lane>>4)*8)*2)
#define B_ADDR(PTR, N0, STR) \
    (s2u(PTR) + (((N0) + (lane&7) + (lane>>4)*8)*(STR) + ((lane>>3)&1)*8)*2)

#define ROW_SOFTMAX(X0,X1,X2,X3, E0,E1,E2,E3)  do {                     \
        float mx_ = fmaxf(fmaxf(X0,X1), fmaxf(X2,X3));                  \
        _Pragma("unroll")                                               \
        for (int o_ = 16; o_; o_ >>= 1)                                 \
            mx_ = fmaxf(mx_, __shfl_xor_sync(0xffffffffu, mx_, o_));    \
        E0 = __expf(X0-mx_); E1 = __expf(X1-mx_);                       \
        E2 = __expf(X2-mx_); E3 = __expf(X3-mx_);                       \
        float s_ = E0+E1+E2+E3;                                         \
        _Pragma("unroll")                                               \
        for (int o_ = 16; o_; o_ >>= 1)                                 \
            s_ += __shfl_xor_sync(0xffffffffu, s_, o_);                 \
        float iv_ = 1.f/s_;                                             \
        E0 *= iv_; E1 *= iv_; E2 *= iv_; E3 *= iv_;                     \
    } while (0)

// ============================================================
// K_prep: fp16 q,k,phi_q (natural), v^T & phi_k^T (staged, coalesced) + means
// grid = BHN*NB = 1024, 256 threads, dynamic smem
// ============================================================
#define STG 72
__global__ void __launch_bounds__(256) k_prep(const float4* __restrict__ q4,
                                              const float4* __restrict__ k4,
                                              const float4* __restrict__ v4) {
    extern __shared__ __align__(16) char psm[];
    float*  redq = (float*)psm;                 // 8*132
    float*  redk = redq + 8*132;                // 8*132
    __half* sVn  = (__half*)(redk + 8*132);     // [64][136] natural
    __half* sPn  = sVn + 64*136;                // [64][136] natural
    __half* sStV = sPn + 64*136;                // [128][STG] transposed stage
    __half* sStP = sStV + 128*STG;              // [128][STG]

    int blk = blockIdx.x, tid = threadIdx.x;
    int c4 = tid & 31, rj = tid >> 5;
    size_t base = (size_t)blk * 64 * 32;
    uint2* qh2 = (uint2*)g_qh;
    uint2* kh2 = (uint2*)g_kh;
    uint2* pq2 = (uint2*)g_phiqh;

    float sq0=0,sq1=0,sq2=0,sq3=0, sk0=0,sk1=0,sk2=0,sk3=0;
#pragma unroll
    for (int i = 0; i < 8; i++) {
        int r = rj + 8*i;
        size_t off = base + (size_t)r*32 + c4;
        float4 a = q4[off];
        sq0+=a.x; sq1+=a.y; sq2+=a.z; sq3+=a.w;
        uint2 ua; ua.x = h2(a.x,a.y); ua.y = h2(a.z,a.w);
        qh2[off] = ua;
        float e0,e1,e2,e3;
        ROW_SOFTMAX(a.x,a.y,a.z,a.w, e0,e1,e2,e3);
        uint2 up; up.x = h2(e0,e1); up.y = h2(e2,e3);
        pq2[off] = up;
        float4 b = k4[off];
        sk0+=b.x; sk1+=b.y; sk2+=b.z; sk3+=b.w;
        uint2 ub; ub.x = h2(b.x,b.y); ub.y = h2(b.z,b.w);
        kh2[off] = ub;
        float f0,f1,f2,f3;
        ROW_SOFTMAX(b.x,b.y,b.z,b.w, f0,f1,f2,f3);
        uint2 uk; uk.x = h2(f0,f1); uk.y = h2(f2,f3);
        *(uint2*)(sPn + r*136 + c4*4) = uk;
        float4 c = v4[off];
        uint2 uv; uv.x = h2(c.x,c.y); uv.y = h2(c.z,c.w);
        *(uint2*)(sVn + r*136 + c4*4) = uv;
    }
    redq[rj*132 + c4*4+0]=sq0; redq[rj*132 + c4*4+1]=sq1;
    redq[rj*132 + c4*4+2]=sq2; redq[rj*132 + c4*4+3]=sq3;
    redk[rj*132 + c4*4+0]=sk0; redk[rj*132 + c4*4+1]=sk1;
    redk[rj*132 + c4*4+2]=sk2; redk[rj*132 + c4*4+3]=sk3;
    __syncthreads();

    int bh = blk >> 5, qb = blk & 31;
    if (tid < DIM) {
        float s = 0.f, t = 0.f;
#pragma unroll
        for (int j = 0; j < 8; j++) { s += redq[j*132 + tid]; t += redk[j*132 + tid]; }
        g_qb[blk*DIM + tid] = s * (1.f/BLK);
        g_kb[blk*DIM + tid] = t * (1.f/BLK);
    }
    // transpose into staging: tid<128 -> V col d ; tid>=128 -> phi_k col d
    {
        int d = tid & 127;
        const __half* srcm = (tid < 128) ? sVn : sPn;
        __half* stg = (tid < 128) ? sStV : sStP;
#pragma unroll
        for (int j = 0; j < 32; j++) {
            __half2 hp = __halves2half2(srcm[(2*j)*136 + d], srcm[(2*j+1)*136 + d]);
            *(uint32_t*)(stg + d*STG + 2*j) = *(uint32_t*)&hp;
        }
    }
    __syncthreads();
    // coalesced copy-out: 2 arrays x 128 rows x 8 uint4 (64 halves) = 2048 uint4
#pragma unroll
    for (int it = 0; it < 8; it++) {
        int idx = tid + it*256;                 // 0..2047
        int arr = idx >> 10;
        int rem = idx & 1023;
        int row = rem >> 3, ch = rem & 7;
        const __half* stg = arr ? sStP : sStV;
        __half* gdst = arr ? g_phikt : g_vth;
        uint4 val = *(const uint4*)(stg + row*STG + ch*8);
        *(uint4*)(gdst + ((size_t)(bh*DIM + row))*LSEQ + qb*64 + ch*8) = val;
    }
}

// ============================================================
// K2: blk_scores + top-4 (exact fp32, lowest-index tie-break)
// ============================================================
__global__ void k_topk() {
    __shared__ float sQ[NB][DIM];
    __shared__ float sK[NB][DIM+1];
    __shared__ float sS[NB][NB];
    int bh = blockIdx.x, tid = threadIdx.x;

    for (int i = tid; i < NB*DIM; i += 1024) {
        sQ[i>>7][i&127] = g_qb[bh*NB*DIM + i];
        sK[i>>7][i&127] = g_kb[bh*NB*DIM + i];
    }
    __syncthreads();
    {
        int qr = tid >> 5, kr = tid & 31;
        float acc = 0.f;
#pragma unroll 8
        for (int kk = 0; kk < DIM; kk++) acc += sQ[qr][kk] * sK[kr][kk];
        sS[qr][kr] = acc;
    }
    __syncthreads();

    int qr = tid >> 5, lane = tid & 31;
    float v = sS[qr][lane];
    int  mi = lane;
#pragma unroll
    for (int t = 0; t < TOP; t++) {
        float bv = v; int bi = mi;
#pragma unroll
        for (int off = 16; off; off >>= 1) {
            float ov = __shfl_xor_sync(0xffffffffu, bv, off);
            int   oi = __shfl_xor_sync(0xffffffffu, bi, off);
            if (ov > bv || (ov == bv && oi < bi)) { bv = ov; bi = oi; }
        }
        if (lane == 0) g_lut[(bh*NB + qr)*TOP + t] = bi;
        if (mi == bi) v = -FLT_MAX;
    }
}

// ============================================================
// K_kvsum: pure GEMM over 2x128-row chunks, ldmatrix, reg-accumulated
// grid = NCH*BHN = 256, 256 threads, 2 blocks/SM
// ============================================================
#define KVS 136
__global__ void __launch_bounds__(256,2) k_kvsum() {
    extern __shared__ __half hsm[];
    __half* sPhiT = hsm;               // [128 d][136 l]
    __half* sVt   = hsm + 128*KVS;     // [128 e][136 l]

    int bid = blockIdx.x;
    int ch  = bid >> 5, bh = bid & 31;
    int tid = threadIdx.x, lane = tid & 31, warp = tid >> 5;

    float acc[16][4];
#pragma unroll
    for (int i = 0; i < 16; i++)
#pragma unroll
        for (int j = 0; j < 4; j++) acc[i][j] = 0.f;
    float ks = 0.f;
    int m0 = warp*16;

    for (int sub = 0; sub < 2; sub++) {
        size_t loff = (size_t)ch*CHL + (size_t)sub*128;
        const __half* pp = g_phikt + (size_t)bh*DIM*LSEQ + loff;
        const __half* vp = g_vth   + (size_t)bh*DIM*LSEQ + loff;
#pragma unroll
        for (int i = 0; i < 8; i++) {
            int idx = tid + 256*i;
            int r = idx >> 4, c8 = (idx & 15)*8;
            cpa16(s2u(sPhiT + r*KVS + c8), pp + (size_t)r*LSEQ + c8);
            cpa16(s2u(sVt   + r*KVS + c8), vp + (size_t)r*LSEQ + c8);
        }
        CP_COMMIT();
        CP_WAIT(0);
        __syncthreads();

        if (tid < DIM) {
            const __half2* p = (const __half2*)(sPhiT + tid*KVS);
#pragma unroll 16
            for (int j = 0; j < 64; j++) { float2 f = __half22float2(p[j]); ks += f.x + f.y; }
        }

        uint32_t aB = A_ADDR(sPhiT, m0, KVS);
#pragma unroll
        for (int kk = 0; kk < 8; kk++) {
            int k0 = kk*16;
            uint32_t a0,a1,a2,a3;
            ldsm4(a0,a1,a2,a3, aB + k0*2);
#pragma unroll
            for (int np = 0; np < 8; np++) {
                uint32_t b00,b01,b10,b11;
                ldsm4(b00,b01,b10,b11, B_ADDR(sVt, np*16, KVS) + k0*2);
                mma16(acc[np*2],   a0,a1,a2,a3, b00,b01);
                mma16(acc[np*2+1], a0,a1,a2,a3, b10,b11);
            }
        }
        __syncthreads();
    }

    if (tid < DIM) g_ksum_part[bid*DIM + tid] = ks;

    int g = lane >> 2, tig = lane & 3;
    float* dst = g_kv_part + (size_t)bid*DIM*DIM;
#pragma unroll
    for (int nt = 0; nt < 16; nt++) {
        int col = nt*8 + 2*tig;
        int row = m0 + g;
        *(float2*)&dst[row*DIM + col]     = make_float2(acc[nt][0], acc[nt][1]);
        *(float2*)&dst[(row+8)*DIM + col] = make_float2(acc[nt][2], acc[nt][3]);
    }
}

// ============================================================
// K_kvw: inline split-K reduce (32 rows) + ksum reduce + M^T GEMM
// grid = BHN*4 = 128, 256 threads
// ============================================================
__global__ void __launch_bounds__(256) k_kvw(const float4* __restrict__ w4) {
    extern __shared__ __half hsm[];
    __half* sKV = hsm;              // [32 d][136 e]
    __half* sW  = hsm + 32*KVS;     // [128 e2][136 e]

    int bh = blockIdx.x >> 2, part = blockIdx.x & 3;
    int m0g = part*32;
    int tid = threadIdx.x, lane = tid & 31, warp = tid >> 5;

    // reduce this block's 32 kv rows over NCH chunks (float4, MLP>=8)
    const float4* kvp4 = (const float4*)g_kv_part;
#pragma unroll
    for (int it = 0; it < 4; it++) {
        int idx = tid + it*256;                 // 0..1023 (32 rows x 32 float4)
        int r = idx >> 5, cc = idx & 31;
        size_t rowoff = (size_t)(m0g + r)*32 + cc;
        float4 s = make_float4(0.f,0.f,0.f,0.f);
#pragma unroll
        for (int ch = 0; ch < NCH; ch++) {
            float4 p = kvp4[(size_t)((ch<<5)|bh)*4096 + rowoff];
            s.x += p.x; s.y += p.y; s.z += p.z; s.w += p.w;
        }
        uint2 u; u.x = h2(s.x, s.y); u.y = h2(s.z, s.w);
        *(uint2*)(sKV + r*KVS + cc*4) = u;
    }
    for (int i4 = tid; i4 < 4096; i4 += 256) {
        int e2 = i4 >> 5, ec = (i4 & 31)*4;
        float4 wv = w4[i4];
        *(uint32_t*)(sW + e2*KVS + ec)     = h2(wv.x, wv.y);
        *(uint32_t*)(sW + e2*KVS + ec + 2) = h2(wv.z, wv.w);
    }
    if (part == 0 && tid < DIM) {
        float t = 0.f;
#pragma unroll
        for (int ch = 0; ch < NCH; ch++) t += g_ksum_part[((ch<<5)|bh)*DIM + tid];
        g_ksum[bh*DIM + tid] = t;
    }
    __syncthreads();

    int mt = warp & 1, ng = warp >> 1;
    int m0 = mt*16;
    float acc[4][4];
#pragma unroll
    for (int i = 0; i < 4; i++)
#pragma unroll
        for (int j = 0; j < 4; j++) acc[i][j] = 0.f;
    uint32_t aB = A_ADDR(sKV, m0, KVS);
#pragma unroll
    for (int kk = 0; kk < 8; kk++) {
        int k0 = kk*16;
        uint32_t a0,a1,a2,a3;
        ldsm4(a0,a1,a2,a3, aB + k0*2);
#pragma unroll
        for (int np = 0; np < 2; np++) {
            uint32_t b00,b01,b10,b11;
            ldsm4(b00,b01,b10,b11, B_ADDR(sW, ng*32 + np*16, KVS) + k0*2);
            mma16(acc[np*2],   a0,a1,a2,a3, b00,b01);
            mma16(acc[np*2+1], a0,a1,a2,a3, b10,b11);
        }
    }
    int g = lane >> 2, tig = lane & 3;
    __half* dst = g_mt + (size_t)bh*DIM*DIM;
    int row = m0g + m0 + g;
#pragma unroll
    for (int nt = 0; nt < 4; nt++) {
        int col = ng*32 + nt*8 + 2*tig;
        dst[col*DIM + row]         = __float2half_rn(acc[nt][0]);
        dst[(col+1)*DIM + row]     = __float2half_rn(acc[nt][1]);
        dst[col*DIM + row + 8]     = __float2half_rn(acc[nt][2]);
        dst[(col+1)*DIM + row + 8] = __float2half_rn(acc[nt][3]);
    }
}

// ============================================================
// K_fused: sparse attention + linear half, fp16 mma + ldmatrix
// grid = BHN*NB = 1024, 256 threads, 114432B smem -> 2 blocks/SM
// ============================================================
#define B0 8704
#define B1 18944
#define B2 29184
#define SPO 39424
#define PST2 264
#define STATS 56320
#define VSTR 72

__global__ void __launch_bounds__(256,2) k_fused(const float* __restrict__ bpr,
                                                 float* __restrict__ out) {
    extern __shared__ __half hsm[];
    __half* sQ = hsm;
    __half* sP = hsm + SPO;
    float* swmax = (float*)(hsm + STATS);
    float* swsum = swmax + 128;
    float* sks   = swsum + 128;
    float* sden  = sks + 128;

    int bid = blockIdx.x, bh = bid >> 5, qb = bid & 31;
    int tid = threadIdx.x, lane = tid & 31, warp = tid >> 5;
    int g = lane >> 2, tig = lane & 3;
    int mt = warp & 3, ns = warp >> 2;

    int lut[4];
#pragma unroll
    for (int t = 0; t < TOP; t++) lut[t] = g_lut[bid*TOP + t];
    if (tid < DIM) sks[tid] = g_ksum[bh*DIM + tid];

#define ISSUE64(SRC, DST) do {                                          \
        const __half* s_ = (SRC);                                       \
        _Pragma("unroll")                                               \
        for (int i_ = 0; i_ < 4; i_++) {                                \
            int idx_ = tid + 256*i_;                                    \
            int r_ = idx_ >> 4, c_ = (idx_ & 15)*8;                     \
            cpa16(s2u((DST) + r_*136 + c_), s_ + r_*128 + c_);          \
        }                                                               \
    } while (0)
#define ISSUE_VT(T, DST) do {                                           \
        const __half* s_ = g_vth + (size_t)bh*DIM*LSEQ + lut[T]*64;     \
        _Pragma("unroll")                                               \
        for (int i_ = 0; i_ < 4; i_++) {                                \
            int idx_ = tid + 256*i_;                                    \
            int r_ = idx_ >> 3, c_ = (idx_ & 7)*8;                      \
            cpa16(s2u((DST) + r_*VSTR + c_), s_ + (size_t)r_*LSEQ + c_);\
        }                                                               \
    } while (0)

    size_t qh_base = ((size_t)bh*LSEQ + (size_t)qb*BLK)*DIM;
    ISSUE64(g_qh + qh_base, sQ);
    ISSUE64(g_kh + ((size_t)bh*LSEQ + lut[0]*BLK)*DIM, hsm + B0);
    CP_COMMIT();                                                  // G1
    ISSUE64(g_kh + ((size_t)bh*LSEQ + lut[1]*BLK)*DIM, hsm + B1);
    CP_COMMIT();                                                  // G2
    ISSUE64(g_kh + ((size_t)bh*LSEQ + lut[2]*BLK)*DIM, hsm + B2);
    CP_COMMIT();                                                  // G3

    float accS[4][4][4];
#pragma unroll
    for (int t = 0; t < 4; t++)
#pragma unroll
        for (int i = 0; i < 4; i++)
#pragma unroll
            for (int j = 0; j < 4; j++) accS[t][i][j] = 0.f;

#define MMA_S(T, KB) do {                                               \
        uint32_t aB_ = A_ADDR(sQ, mt*16, 136);                          \
        uint32_t bB_ = B_ADDR((KB), ns*32, 136);                        \
        _Pragma("unroll")                                               \
        for (int kk = 0; kk < 8; kk++) {                                \
            int k0 = kk*16;                                             \
            uint32_t a0,a1,a2,a3, b00,b01,b10,b11;                      \
            ldsm4(a0,a1,a2,a3, aB_ + k0*2);                             \
            ldsm4(b00,b01,b10,b11, bB_ + k0*2);                         \
            mma16(accS[T][0], a0,a1,a2,a3, b00,b01);                    \
            mma16(accS[T][1], a0,a1,a2,a3, b10,b11);                    \
            ldsm4(b00,b01,b10,b11, bB_ + 16*136*2 + k0*2);              \
            mma16(accS[T][2], a0,a1,a2,a3, b00,b01);                    \
            mma16(accS[T][3], a0,a1,a2,a3, b10,b11);                    \
        }                                                               \
    } while (0)

    CP_WAIT(2); __syncthreads();
    MMA_S(0, hsm + B0); __syncthreads();
    ISSUE64(g_kh + ((size_t)bh*LSEQ + lut[3]*BLK)*DIM, hsm + B0); CP_COMMIT();  // G4
    CP_WAIT(2); __syncthreads();
    MMA_S(1, hsm + B1); __syncthreads();
    ISSUE_VT(0, hsm + B1); CP_COMMIT();                                          // G5
    CP_WAIT(2); __syncthreads();
    MMA_S(2, hsm + B2); __syncthreads();
    ISSUE_VT(1, hsm + B2); CP_COMMIT();                                          // G6
    CP_WAIT(2); __syncthreads();
    MMA_S(3, hsm + B0); __syncthreads();
    ISSUE_VT(2, hsm + B0); CP_COMMIT();                                          // G7

    // ---- softmax over registers with cross-warp stats ----
    const float scale = 0.08838834764831845f;
    int row0 = mt*16 + g, row1 = row0 + 8;
    {
        float m0v = -FLT_MAX, m1v = -FLT_MAX;
#pragma unroll
        for (int t = 0; t < 4; t++)
#pragma unroll
            for (int nt = 0; nt < 4; nt++) {
                m0v = fmaxf(m0v, fmaxf(accS[t][nt][0], accS[t][nt][1]));
                m1v = fmaxf(m1v, fmaxf(accS[t][nt][2], accS[t][nt][3]));
            }
        m0v = fmaxf(m0v, __shfl_xor_sync(0xffffffffu, m0v, 1));
        m0v = fmaxf(m0v, __shfl_xor_sync(0xffffffffu, m0v, 2));
        m1v = fmaxf(m1v, __shfl_xor_sync(0xffffffffu, m1v, 1));
        m1v = fmaxf(m1v, __shfl_xor_sync(0xffffffffu, m1v, 2));
        if (tig == 0) { swmax[row0*2+ns] = m0v; swmax[row1*2+ns] = m1v; }
    }
    __syncthreads();
    {
        float gm0 = fmaxf(swmax[row0*2], swmax[row0*2+1]);
        float gm1 = fmaxf(swmax[row1*2], swmax[row1*2+1]);
        float s0 = 0.f, s1 = 0.f;
#pragma unroll
        for (int t = 0; t < 4; t++)
#pragma unroll
            for (int nt = 0; nt < 4; nt++) {
                float e0 = __expf((accS[t][nt][0]-gm0)*scale);
                float e1 = __expf((accS[t][nt][1]-gm0)*scale);
                float e2 = __expf((accS[t][nt][2]-gm1)*scale);
                float e3 = __expf((accS[t][nt][3]-gm1)*scale);
                s0 += e0 + e1; s1 += e2 + e3;
                int col = t*64 + ns*32 + nt*8 + 2*tig;
                *(uint32_t*)(sP + row0*PST2 + col) = h2(e0, e1);
                *(uint32_t*)(sP + row1*PST2 + col) = h2(e2, e3);
            }
        s0 += __shfl_xor_sync(0xffffffffu, s0, 1);
        s0 += __shfl_xor_sync(0xffffffffu, s0, 2);
        s1 += __shfl_xor_sync(0xffffffffu, s1, 1);
        s1 += __shfl_xor_sync(0xffffffffu, s1, 2);
        if (tig == 0) { swsum[row0*2+ns] = s0; swsum[row1*2+ns] = s1; }
    }

    // ---- PV ----
    float oac[8][4];
#pragma unroll
    for (int i = 0; i < 8; i++)
#pragma unroll
        for (int j = 0; j < 4; j++) oac[i][j] = 0.f;

#define MMA_PV(T, VB) do {                                              \
        uint32_t aB_ = A_ADDR(sP, mt*16, PST2) + (T)*64*2;              \
        _Pragma("unroll")                                               \
        for (int kk = 0; kk < 4; kk++) {                                \
            int k0 = kk*16;                                             \
            uint32_t a0,a1,a2,a3;                                       \
            ldsm4(a0,a1,a2,a3, aB_ + k0*2);                             \
            _Pragma("unroll")                                           \
            for (int np = 0; np < 4; np++) {                            \
                uint32_t b00,b01,b10,b11;                               \
                ldsm4(b00,b01,b10,b11, B_ADDR((VB), ns*64+np*16, VSTR) + k0*2); \
                mma16(oac[np*2],   a0,a1,a2,a3, b00,b01);               \
                mma16(oac[np*2+1], a0,a1,a2,a3, b10,b11);               \
            }                                                           \
        }                                                               \
    } while (0)

    CP_WAIT(2); __syncthreads();            // V0 ready
    MMA_PV(0, hsm + B1); __syncthreads();
    ISSUE_VT(3, hsm + B1); CP_COMMIT();                                          // G8
    CP_WAIT(2); __syncthreads();            // V1 ready
    MMA_PV(1, hsm + B2);
    __syncthreads();
    ISSUE64(g_phiqh + qh_base, hsm + B2); CP_COMMIT();                           // G9
    CP_WAIT(2); __syncthreads();            // V2 ready (G7)
    MMA_PV(2, hsm + B0);
    __syncthreads();                        // base/sQ + B0 dead across all warps
    {
        const __half* s_ = g_mt + (size_t)bh*DIM*DIM;
#pragma unroll
        for (int i_ = 0; i_ < 8; i_++) {
            int idx_ = tid + 256*i_;
            int r_ = idx_ >> 4, c_ = (idx_ & 15)*8;
            cpa16(s2u(hsm + r_*136 + c_), s_ + r_*128 + c_);
        }
        CP_COMMIT();                                                             // G10
    }
    CP_WAIT(2); __syncthreads();            // V3 ready (G8)
    MMA_PV(3, hsm + B1);

    // ---- den = phi_q . ksum ----
    CP_WAIT(1); __syncthreads();            // phi_q ready (G9)
    for (int r = warp; r < BLK; r += 8) {
        const __half* pr = hsm + B2 + r*136;
        float dp = __half2float(pr[lane])    * sks[lane]
                 + __half2float(pr[lane+32]) * sks[lane+32]
                 + __half2float(pr[lane+64]) * sks[lane+64]
                 + __half2float(pr[lane+96]) * sks[lane+96];
#pragma unroll
        for (int o = 16; o; o >>= 1) dp += __shfl_xor_sync(0xffffffffu, dp, o);
        if (lane == 0) sden[r] = 1.f/(1e-5f + dp);
    }
    CP_WAIT(0);                             // Mt ready (G10)
    __syncthreads();

    // ---- linear GEMM: o_pre = phi_q @ M ----
    float acc2[8][4];
#pragma unroll
    for (int i = 0; i < 8; i++)
#pragma unroll
        for (int j = 0; j < 4; j++) acc2[i][j] = 0.f;
    {
        uint32_t aB_ = A_ADDR(hsm + B2, mt*16, 136);
#pragma unroll
        for (int kk = 0; kk < 8; kk++) {
            int k0 = kk*16;
            uint32_t a0,a1,a2,a3;
            ldsm4(a0,a1,a2,a3, aB_ + k0*2);
#pragma unroll
            for (int np = 0; np < 4; np++) {
                uint32_t b00,b01,b10,b11;
                ldsm4(b00,b01,b10,b11, B_ADDR(hsm, ns*64+np*16, 136) + k0*2);
                mma16(acc2[np*2],   a0,a1,a2,a3, b00,b01);
                mma16(acc2[np*2+1], a0,a1,a2,a3, b10,b11);
            }
        }
    }

    // ---- epilogue: out = o_s + o_l + bias ----
    float inv0 = 1.f/(swsum[row0*2] + swsum[row0*2+1]);
    float inv1 = 1.f/(swsum[row1*2] + swsum[row1*2+1]);
    float dn0 = sden[row0], dn1 = sden[row1];
    size_t obase = ((size_t)bh*LSEQ + (size_t)qb*BLK)*DIM;
#pragma unroll
    for (int nt = 0; nt < 8; nt++) {
        int col = ns*64 + nt*8 + 2*tig;
        float bb0 = bpr[col], bb1 = bpr[col+1];
        float* op0 = out + obase + (size_t)row0*DIM + col;
        float* op1 = out + obase + (size_t)row1*DIM + col;
        *(float2*)op0 = make_float2(oac[nt][0]*inv0 + acc2[nt][0]*dn0 + bb0,
                                    oac[nt][1]*inv0 + acc2[nt][1]*dn0 + bb1);
        *(float2*)op1 = make_float2(oac[nt][2]*inv1 + acc2[nt][2]*dn1 + bb0,
                                    oac[nt][3]*inv1 + acc2[nt][3]*dn1 + bb1);
    }
}

// ============================================================
extern "C" void kernel_launch(void* const* d_in, const int* in_sizes, int n_in,
                              void* d_out, int out_size) {
    const float* q = (const float*)d_in[0];
    const float* k = (const float*)d_in[1];
    const float* v = (const float*)d_in[2];
    const float* w = (const float*)d_in[3];
    const float* b = (const float*)d_in[4];
    float* out = (float*)d_out;

    int smP  = (2*8*132)*4 + (2*64*136 + 2*128*STG)*2;   // 80128
    int smKV = 2*128*KVS*2;                               // 69632
    int smKW = (32*KVS + 128*KVS)*2;                      // 43520
    int smF  = STATS*2 + 448*4;                           // 114432
    cudaFuncSetAttribute(k_prep,  cudaFuncAttributeMaxDynamicSharedMemorySize, smP);
    cudaFuncSetAttribute(k_kvsum, cudaFuncAttributeMaxDynamicSharedMemorySize, smKV);
    cudaFuncSetAttribute(k_kvw,   cudaFuncAttributeMaxDynamicSharedMemorySize, smKW);
    cudaFuncSetAttribute(k_fused, cudaFuncAttributeMaxDynamicSharedMemorySize, smF);

    k_prep<<<BHN*NB, 256, smP>>>((const float4*)q, (const float4*)k, (const float4*)v);
    k_topk<<<BHN, 1024>>>();
    k_kvsum<<<NCH*BHN, 256, smKV>>>();
    k_kvw<<<BHN*4, 256, smKW>>>((const float4*)w);
    k_fused<<<BHN*NB, 256, smF>>>(b, out);
}